// round 15
// baseline (speedup 1.0000x reference)
#include <cuda_runtime.h>
#include <cuda_fp16.h>
#include <math.h>
#include <stdint.h>

#define BT   8192
#define TT   4096
#define DIM  1024

// ---------------- scratch (device globals) ----------------
__device__ __half g_xh [BT * DIM];          // LN1 out fp16 (GEMM A + residual)
__device__ __half g_qkv[BT * 3 * DIM];      // fused q|k|v
__device__ __half g_cat[BT * 2 * DIM];      // attn out (fwd|rev)
__device__ __half g_fbh[BT * DIM];          // Wfb out fp16 (pre-LN2)
__device__ __half g_yh [BT * DIM];          // LN2 out fp16
__device__ __half g_wqkvT[3 * DIM * DIM];   // [3072][1024] = W^T fp16
__device__ __half g_wfbT [DIM * 2 * DIM];   // [1024][2048]
__device__ __half g_woT  [DIM * DIM];       // [1024][1024]
__device__ float  g_bqkv [3 * DIM];
__device__ int    g_cnt  [BT / 128];        // row-block completion counters (self-resetting)

// ---------------- helpers ----------------
__device__ __forceinline__ uint32_t smem_u32(const void* p) {
    uint32_t a;
    asm("{ .reg .u64 t; cvta.to.shared.u64 t, %1; cvt.u32.u64 %0, t; }" : "=r"(a) : "l"(p));
    return a;
}
__device__ __forceinline__ float gelu_exact(float x) {
    return 0.5f * x * (1.0f + erff(x * 0.7071067811865475f));
}
__device__ __forceinline__ float block_sum_256(float v, float* sh) {
    #pragma unroll
    for (int o = 16; o; o >>= 1) v += __shfl_xor_sync(0xffffffffu, v, o);
    int w = threadIdx.x >> 5;
    if ((threadIdx.x & 31) == 0) sh[w] = v;
    __syncthreads();
    if (threadIdx.x < 8) {
        float t = sh[threadIdx.x];
        #pragma unroll
        for (int o = 4; o; o >>= 1) t += __shfl_xor_sync(0xffu, t, o);
        if (threadIdx.x == 0) sh[0] = t;
    }
    __syncthreads();
    float r = sh[0];
    __syncthreads();
    return r;
}

__device__ __forceinline__ void mma_fp16(float* c, const uint32_t* a, const uint32_t* b) {
    asm volatile(
        "mma.sync.aligned.m16n8k16.row.col.f32.f16.f16.f32 "
        "{%0,%1,%2,%3}, {%4,%5,%6,%7}, {%8,%9}, {%0,%1,%2,%3};"
        : "+f"(c[0]), "+f"(c[1]), "+f"(c[2]), "+f"(c[3])
        : "r"(a[0]), "r"(a[1]), "r"(a[2]), "r"(a[3]), "r"(b[0]), "r"(b[1]));
}
#define LDSM4(r0, r1, r2, r3, addr) \
    asm volatile("ldmatrix.sync.aligned.m8n8.x4.shared.b16 {%0,%1,%2,%3}, [%4];" \
        : "=r"(r0), "=r"(r1), "=r"(r2), "=r"(r3) : "r"(addr))

#define CP16(dst, src) \
    asm volatile("cp.async.cg.shared.global [%0], [%1], 16;" :: "r"(dst), "l"(src))
#define CP_COMMIT() asm volatile("cp.async.commit_group;" ::: "memory")
#define CP_WAIT1()  asm volatile("cp.async.wait_group 1;" ::: "memory")

// ---------------- LayerNorm row body (prologue LN1) ----------------
__device__ __forceinline__ void ln_row(const float* __restrict__ in,
                                       const float* __restrict__ g, const float* __restrict__ b,
                                       __half* __restrict__ outh, int row, float* sh) {
    float4 v = ((const float4*)in)[(size_t)row * (DIM / 4) + threadIdx.x];
    float s = block_sum_256(v.x + v.y + v.z + v.w, sh);
    float mean = s * (1.0f / DIM);
    float dx = v.x - mean, dy = v.y - mean, dz = v.z - mean, dw = v.w - mean;
    float sq = block_sum_256(dx*dx + dy*dy + dz*dz + dw*dw, sh);
    float scale = rsqrtf(sq * (1.0f / DIM) + 1e-6f);
    float4 gv = ((const float4*)g)[threadIdx.x];
    float4 bv = ((const float4*)b)[threadIdx.x];
    __half2* ph = (__half2*)(outh + (size_t)row * DIM);
    ph[2 * threadIdx.x + 0] = __floats2half2_rn(dx * scale * gv.x + bv.x, dy * scale * gv.y + bv.y);
    ph[2 * threadIdx.x + 1] = __floats2half2_rn(dz * scale * gv.z + bv.z, dw * scale * gv.w + bv.w);
}

// ---------------- prologue: LN1 + weight transpose + bias concat (1 launch) ----------------
__global__ void prologue(const float* __restrict__ inp,
                         const float* __restrict__ Wq, const float* __restrict__ Wk,
                         const float* __restrict__ Wv, const float* __restrict__ Wfb,
                         const float* __restrict__ Wo,
                         __half* __restrict__ wqkvT, __half* __restrict__ wfbT,
                         __half* __restrict__ woT,
                         const float* __restrict__ bq, const float* __restrict__ bk,
                         const float* __restrict__ bv, float* __restrict__ bqkv,
                         const float* __restrict__ g1, const float* __restrict__ b1,
                         __half* __restrict__ xhp) {
    __shared__ float sh[8];
    __shared__ float t[32][33];
    int bid = blockIdx.x;
    if (bid < BT) {                        // LN1 row
        ln_row(inp, g1, b1, xhp, bid, sh);
        return;
    }
    int idx = bid - BT;
    int xblk = idx & 31;
    int seg  = idx >> 5;                   // 0..192
    int tid = threadIdx.x;
    if (seg == 192) {                      // bias concat
        int i = xblk * 256 + tid;
        if (i < DIM) bqkv[i] = bq[i];
        else if (i < 2 * DIM) bqkv[i] = bk[i - DIM];
        else if (i < 3 * DIM) bqkv[i] = bv[i - 2 * DIM];
        return;
    }
    const float* W;
    __half* WT;
    int R, rb;
    if (seg < 32)       { W = Wq;  WT = wqkvT;                 R = DIM;     rb = seg; }
    else if (seg < 64)  { W = Wk;  WT = wqkvT + DIM * DIM;     R = DIM;     rb = seg - 32; }
    else if (seg < 96)  { W = Wv;  WT = wqkvT + 2 * DIM * DIM; R = DIM;     rb = seg - 64; }
    else if (seg < 160) { W = Wfb; WT = wfbT;                  R = 2 * DIM; rb = seg - 96; }
    else                { W = Wo;  WT = woT;                   R = DIM;     rb = seg - 160; }
    int c0 = xblk * 32, r0 = rb * 32;
    int x = tid & 31, y = tid >> 5;
    #pragma unroll
    for (int i = 0; i < 32; i += 8)
        t[y + i][x] = W[(size_t)(r0 + y + i) * DIM + c0 + x];
    __syncthreads();
    #pragma unroll
    for (int i = 0; i < 32; i += 8)
        WT[(size_t)(c0 + y + i) * R + r0 + x] = __float2half_rn(t[x][y + i]);
}

// ---------------- fp16 tensor-core GEMM (optionally LN2-fused epilogue) ----------------
#define ASH     72
#define ASTAGE  (128 * ASH)
#define BSTAGE  (128 * ASH)
#define GSMEM_BYTES (3 * (ASTAGE + BSTAGE) * 2)   // 110592 → 2 CTAs/SM

template<typename OUT, bool GELU, bool LN2F>
__global__ void __launch_bounds__(128, 2)
gemm_h(const __half* __restrict__ A, const __half* __restrict__ Bt,
       const float* __restrict__ bias, OUT* __restrict__ C, int N, int K,
       const __half* __restrict__ resid, const float* __restrict__ g2,
       const float* __restrict__ b2, __half* __restrict__ yout, int* __restrict__ cnt) {
    extern __shared__ __align__(16) __half hsm[];
    __half* As = hsm;
    __half* Bs = hsm + 3 * ASTAGE;

    int tid = threadIdx.x;
    int wid = tid >> 5, lane = tid & 31;
    int wm = (wid >> 1) * 64;
    int wn = (wid & 1) * 64;
    int g = lane >> 2, t4 = lane & 3;
    int m0 = blockIdx.y << 7, n0 = blockIdx.x << 7;

    int arow  = (lane & 7) | (((lane >> 3) & 1) << 3);
    int akoff = (lane >> 4) << 3;
    int brow  = (lane & 7) | ((lane >> 4) << 3);
    int bkoff = ((lane >> 3) & 1) << 3;
    uint32_t a_lane = smem_u32(As) + (uint32_t)(((wm + arow) * ASH + akoff) << 1);
    uint32_t b_lane = smem_u32(Bs) + (uint32_t)(((wn + brow) * ASH + bkoff) << 1);

    float acc[4][8][4];
    #pragma unroll
    for (int i = 0; i < 4; i++)
        #pragma unroll
        for (int j = 0; j < 8; j++)
            #pragma unroll
            for (int q = 0; q < 4; q++) acc[i][j][q] = 0.0f;

    auto cp_stage = [&](int s, int c) {
        const __half* Ab = A + (size_t)m0 * K + c * 64;
        const __half* Bb = Bt + (size_t)n0 * K + c * 64;
        #pragma unroll
        for (int j = 0; j < 8; j++) {
            int idx = tid + (j << 7);
            int r = idx >> 3, cc = (idx & 7) << 3;
            CP16(smem_u32(As + s * ASTAGE + r * ASH + cc), Ab + (size_t)r * K + cc);
            CP16(smem_u32(Bs + s * BSTAGE + r * ASH + cc), Bb + (size_t)r * K + cc);
        }
        CP_COMMIT();
    };

    int NC = K >> 6;
    cp_stage(0, 0);
    cp_stage(1, 1);

    for (int c = 0; c < NC; c++) {
        CP_WAIT1();
        __syncthreads();
        if (c + 2 < NC) cp_stage((c + 2) % 3, c + 2);
        else CP_COMMIT();

        int s = c % 3;
        uint32_t as_s = a_lane + (uint32_t)(s * ASTAGE * 2);
        uint32_t bs_s = b_lane + (uint32_t)(s * BSTAGE * 2);
        #pragma unroll
        for (int kk = 0; kk < 4; kk++) {
            uint32_t af[4][4], bf[8][2];
            #pragma unroll
            for (int mt = 0; mt < 4; mt++)
                LDSM4(af[mt][0], af[mt][1], af[mt][2], af[mt][3],
                      as_s + (uint32_t)(((mt * 16 * ASH) + kk * 16) << 1));
            #pragma unroll
            for (int np = 0; np < 4; np++)
                LDSM4(bf[2 * np][0], bf[2 * np][1], bf[2 * np + 1][0], bf[2 * np + 1][1],
                      bs_s + (uint32_t)(((np * 16 * ASH) + kk * 16) << 1));
            #pragma unroll
            for (int mt = 0; mt < 4; mt++)
                #pragma unroll
                for (int nt = 0; nt < 8; nt++)
                    mma_fp16(acc[mt][nt], af[mt], bf[nt]);
        }
    }

    #pragma unroll
    for (int mt = 0; mt < 4; mt++) {
        int row = m0 + wm + mt * 16 + g;
        #pragma unroll
        for (int nt = 0; nt < 8; nt++) {
            int col = n0 + wn + nt * 8 + 2 * t4;
            float b0 = bias[col], b1 = bias[col + 1];
            float v00 = acc[mt][nt][0] + b0, v01 = acc[mt][nt][1] + b1;
            float v10 = acc[mt][nt][2] + b0, v11 = acc[mt][nt][3] + b1;
            if (GELU) {
                v00 = gelu_exact(v00); v01 = gelu_exact(v01);
                v10 = gelu_exact(v10); v11 = gelu_exact(v11);
            }
            if (sizeof(OUT) == 2) {
                *(__half2*)((__half*)C + (size_t)row * N + col) = __floats2half2_rn(v00, v01);
                *(__half2*)((__half*)C + (size_t)(row + 8) * N + col) = __floats2half2_rn(v10, v11);
            } else {
                *(float2*)((float*)C + (size_t)row * N + col) = make_float2(v00, v01);
                *(float2*)((float*)C + (size_t)(row + 8) * N + col) = make_float2(v10, v11);
            }
        }
    }

    // ---- fused LN2 over this 128-row block, done by the LAST CTA of the row ----
    if (LN2F) {
        __threadfence();                   // make our fbh stores visible gpu-wide
        __syncthreads();
        __shared__ int lastflag;
        if (tid == 0) {
            int prev = atomicAdd(&cnt[blockIdx.y], 1);
            lastflag = (prev == (int)gridDim.x - 1);
            if (lastflag) cnt[blockIdx.y] = 0;   // replay-safe self-reset
        }
        __syncthreads();
        if (lastflag) {
            __threadfence();
            // 4 warps x 32 rows; warp-per-row, coalesced half2 accesses
            for (int r = 0; r < 32; r++) {
                int row = m0 + wid * 32 + r;
                const __half* frow = (const __half*)C + (size_t)row * N;
                const __half* rrow = resid + (size_t)row * DIM;
                float sum = 0.0f, ssq = 0.0f;
                #pragma unroll
                for (int j = 0; j < 16; j++) {
                    int col = j * 64 + lane * 2;
                    float2 a = __half22float2(*(const __half2*)(frow + col));
                    float2 rr = __half22float2(*(const __half2*)(rrow + col));
                    float vx = a.x + rr.x, vy = a.y + rr.y;
                    sum += vx + vy;
                    ssq += vx * vx + vy * vy;
                }
                #pragma unroll
                for (int o = 16; o; o >>= 1) {
                    sum += __shfl_xor_sync(0xffffffffu, sum, o);
                    ssq += __shfl_xor_sync(0xffffffffu, ssq, o);
                }
                float mean = sum * (1.0f / DIM);
                float var = ssq * (1.0f / DIM) - mean * mean;
                float sc = rsqrtf(var + 1e-6f);
                __half2* yrow = (__half2*)(yout + (size_t)row * DIM);
                #pragma unroll
                for (int j = 0; j < 16; j++) {
                    int col = j * 64 + lane * 2;
                    float2 a = __half22float2(*(const __half2*)(frow + col));
                    float2 rr = __half22float2(*(const __half2*)(rrow + col));
                    float2 gv = *(const float2*)(g2 + col);
                    float2 bv = *(const float2*)(b2 + col);
                    float ox = (a.x + rr.x - mean) * sc * gv.x + bv.x;
                    float oy = (a.y + rr.y - mean) * sc * gv.y + bv.y;
                    yrow[col >> 1] = __floats2half2_rn(ox, oy);
                }
            }
        }
    }
}

// ---------------- local windowed attention (round-14 version) ----------------
__global__ void attn_kernel(const __half* __restrict__ qkv, __half* __restrict__ cat) {
    int w = (blockIdx.x * blockDim.x + threadIdx.x) >> 5;
    int lane = threadIdx.x & 31;
    int dir = w & 1;
    int hp  = (w >> 1) & 7;
    int tg  = w >> 4;
    int b   = tg >> 12;
    int t   = tg & (TT - 1);
    int step = dir ? 1 : -1;
    int base = b << 12;
    int off = hp * 128 + (lane >> 4) * 64 + (lane & 15) * 4;

    int tq = t + step;
    float4 qv = make_float4(0.f, 0.f, 0.f, 0.f);
    if (tq >= 0 && tq < TT) {
        uint2 raw = *(const uint2*)(qkv + (size_t)(base + tq) * 3072 + off);
        float2 a = __half22float2(*(__half2*)&raw.x);
        float2 c = __half22float2(*(__half2*)&raw.y);
        qv = make_float4(a.x, a.y, c.x, c.y);
    }

    float s[3];
    uint2 vr[3];
    #pragma unroll
    for (int j = 0; j < 3; j++) {
        int tk = t + step * j;
        float4 kv = make_float4(0.f, 0.f, 0.f, 0.f);
        uint2 vraw = make_uint2(0u, 0u);
        if (tk >= 0 && tk < TT) {
            const __half* rp = qkv + (size_t)(base + tk) * 3072 + off;
            uint2 kraw = *(const uint2*)(rp + DIM);
            vraw = *(const uint2*)(rp + 2 * DIM);
            float2 k0 = __half22float2(*(__half2*)&kraw.x);
            float2 k1 = __half22float2(*(__half2*)&kraw.y);
            kv = make_float4(k0.x, k0.y, k1.x, k1.y);
        }
        float p = qv.x * kv.x + qv.y * kv.y + qv.z * kv.z + qv.w * kv.w;
        #pragma unroll
        for (int o = 8; o; o >>= 1) p += __shfl_xor_sync(0xffffffffu, p, o);
        s[j] = p * 0.125f;
        vr[j] = vraw;
    }
    float m  = fmaxf(s[0], fmaxf(s[1], s[2]));
    float e0 = __expf(s[0] - m), e1 = __expf(s[1] - m), e2 = __expf(s[2] - m);
    float inv = __fdividef(1.0f, e0 + e1 + e2);
    __half2 w0 = __float2half2_rn(e0 * inv);
    __half2 w1 = __float2half2_rn(e1 * inv);
    __half2 w2 = __float2half2_rn(e2 * inv);
    __half2 lo = __hmul2(w0, *(__half2*)&vr[0].x);
    lo = __hfma2(w1, *(__half2*)&vr[1].x, lo);
    lo = __hfma2(w2, *(__half2*)&vr[2].x, lo);
    __half2 hi = __hmul2(w0, *(__half2*)&vr[0].y);
    hi = __hfma2(w1, *(__half2*)&vr[1].y, hi);
    hi = __hfma2(w2, *(__half2*)&vr[2].y, hi);
    uint2 outp;
    *(__half2*)&outp.x = lo;
    *(__half2*)&outp.y = hi;
    *(uint2*)(cat + (size_t)(base + t) * (2 * DIM) + dir * DIM + off) = outp;
}

// ---------------- launch ----------------
extern "C" void kernel_launch(void* const* d_in, const int* in_sizes, int n_in,
                              void* d_out, int out_size) {
    const float* inp = (const float*)d_in[0];
    const float* Wq  = (const float*)d_in[1];
    const float* bq  = (const float*)d_in[2];
    const float* Wk  = (const float*)d_in[3];
    const float* bk  = (const float*)d_in[4];
    const float* Wv  = (const float*)d_in[5];
    const float* bv  = (const float*)d_in[6];
    const float* Wfb = (const float*)d_in[7];
    const float* bfb = (const float*)d_in[8];
    const float* Wo  = (const float*)d_in[9];
    const float* bo  = (const float*)d_in[10];
    const float* g1  = (const float*)d_in[11];
    const float* b1  = (const float*)d_in[12];
    const float* g2  = (const float*)d_in[13];
    const float* b2  = (const float*)d_in[14];
    float* out = (float*)d_out;

    float *bqkvp;
    int* cntp;
    __half *xhp, *qkvp, *catp, *fbhp, *yhp, *wqkvT, *wfbT, *woT;
    cudaGetSymbolAddress((void**)&xhp,   g_xh);
    cudaGetSymbolAddress((void**)&qkvp,  g_qkv);
    cudaGetSymbolAddress((void**)&catp,  g_cat);
    cudaGetSymbolAddress((void**)&fbhp,  g_fbh);
    cudaGetSymbolAddress((void**)&yhp,   g_yh);
    cudaGetSymbolAddress((void**)&wqkvT, g_wqkvT);
    cudaGetSymbolAddress((void**)&wfbT,  g_wfbT);
    cudaGetSymbolAddress((void**)&woT,   g_woT);
    cudaGetSymbolAddress((void**)&bqkvp, g_bqkv);
    cudaGetSymbolAddress((void**)&cntp,  g_cnt);

    cudaFuncSetAttribute(gemm_h<__half, false, false>, cudaFuncAttributeMaxDynamicSharedMemorySize, GSMEM_BYTES);
    cudaFuncSetAttribute(gemm_h<__half, false, true>,  cudaFuncAttributeMaxDynamicSharedMemorySize, GSMEM_BYTES);
    cudaFuncSetAttribute(gemm_h<float, true, false>,   cudaFuncAttributeMaxDynamicSharedMemorySize, GSMEM_BYTES);

    // LN1 + weight transpose + bias concat, one launch
    prologue<<<BT + 193 * 32, 256>>>(inp, Wq, Wk, Wv, Wfb, Wo,
                                     wqkvT, wfbT, woT, bq, bk, bv, bqkvp,
                                     g1, b1, xhp);

    // fused QKV projection: [8192,1024] @ [1024,3072]
    gemm_h<__half, false, false><<<dim3(3 * DIM / 128, BT / 128), 128, GSMEM_BYTES>>>(
        xhp, wqkvT, bqkvp, qkvp, 3 * DIM, DIM,
        nullptr, nullptr, nullptr, nullptr, nullptr);

    // attention
    attn_kernel<<<BT * 16 / 8, 256>>>(qkvp, catp);

    // feedback projection (K=2048) with FUSED residual+LN2 epilogue
    gemm_h<__half, false, true><<<dim3(DIM / 128, BT / 128), 128, GSMEM_BYTES>>>(
        catp, wfbT, bfb, fbhp, DIM, 2 * DIM,
        xhp, g2, b2, yhp, cntp);

    // output projection + GELU (fp32 out)
    gemm_h<float, true, false><<<dim3(DIM / 128, BT / 128), 128, GSMEM_BYTES>>>(
        yhp, woT, bo, out, DIM, DIM,
        nullptr, nullptr, nullptr, nullptr, nullptr);
}

// round 16
// speedup vs baseline: 1.0354x; 1.0354x over previous
#include <cuda_runtime.h>
#include <cuda_fp16.h>
#include <math.h>
#include <stdint.h>

#define BT   8192
#define TT   4096
#define DIM  1024

// ---------------- scratch (device globals) ----------------
__device__ __half g_xh [BT * DIM];          // LN1 out fp16 (GEMM A + residual)
__device__ __half g_qkv[BT * 3 * DIM];      // fused q|k|v
__device__ __half g_cat[BT * 2 * DIM];      // attn out (fwd|rev)
__device__ __half g_fbh[BT * DIM];          // Wfb out fp16 (pre-LN2)
__device__ __half g_yh [BT * DIM];          // LN2 out fp16
__device__ __half g_wqkvT[3 * DIM * DIM];   // [3072][1024] = W^T fp16
__device__ __half g_wfbT [DIM * 2 * DIM];   // [1024][2048]
__device__ __half g_woT  [DIM * DIM];       // [1024][1024]
__device__ float  g_bqkv [3 * DIM];

// ---------------- helpers ----------------
__device__ __forceinline__ uint32_t smem_u32(const void* p) {
    uint32_t a;
    asm("{ .reg .u64 t; cvta.to.shared.u64 t, %1; cvt.u32.u64 %0, t; }" : "=r"(a) : "l"(p));
    return a;
}
__device__ __forceinline__ float gelu_exact(float x) {
    return 0.5f * x * (1.0f + erff(x * 0.7071067811865475f));
}
__device__ __forceinline__ float block_sum_256(float v, float* sh) {
    #pragma unroll
    for (int o = 16; o; o >>= 1) v += __shfl_xor_sync(0xffffffffu, v, o);
    int w = threadIdx.x >> 5;
    if ((threadIdx.x & 31) == 0) sh[w] = v;
    __syncthreads();
    if (threadIdx.x < 8) {
        float t = sh[threadIdx.x];
        #pragma unroll
        for (int o = 4; o; o >>= 1) t += __shfl_xor_sync(0xffu, t, o);
        if (threadIdx.x == 0) sh[0] = t;
    }
    __syncthreads();
    float r = sh[0];
    __syncthreads();
    return r;
}

__device__ __forceinline__ void mma_fp16(float* c, const uint32_t* a, const uint32_t* b) {
    asm volatile(
        "mma.sync.aligned.m16n8k16.row.col.f32.f16.f16.f32 "
        "{%0,%1,%2,%3}, {%4,%5,%6,%7}, {%8,%9}, {%0,%1,%2,%3};"
        : "+f"(c[0]), "+f"(c[1]), "+f"(c[2]), "+f"(c[3])
        : "r"(a[0]), "r"(a[1]), "r"(a[2]), "r"(a[3]), "r"(b[0]), "r"(b[1]));
}
#define LDSM4(r0, r1, r2, r3, addr) \
    asm volatile("ldmatrix.sync.aligned.m8n8.x4.shared.b16 {%0,%1,%2,%3}, [%4];" \
        : "=r"(r0), "=r"(r1), "=r"(r2), "=r"(r3) : "r"(addr))

#define CP16(dst, src) \
    asm volatile("cp.async.cg.shared.global [%0], [%1], 16;" :: "r"(dst), "l"(src))
#define CP_COMMIT() asm volatile("cp.async.commit_group;" ::: "memory")
#define CP_WAIT1()  asm volatile("cp.async.wait_group 1;" ::: "memory")

// ---------------- LayerNorm row body (LN1: fp32 in -> fp16 out) ----------------
__device__ __forceinline__ void ln_row(const float* __restrict__ in,
                                       const float* __restrict__ g, const float* __restrict__ b,
                                       __half* __restrict__ outh, int row, float* sh) {
    float4 v = ((const float4*)in)[(size_t)row * (DIM / 4) + threadIdx.x];
    float s = block_sum_256(v.x + v.y + v.z + v.w, sh);
    float mean = s * (1.0f / DIM);
    float dx = v.x - mean, dy = v.y - mean, dz = v.z - mean, dw = v.w - mean;
    float sq = block_sum_256(dx*dx + dy*dy + dz*dz + dw*dw, sh);
    float scale = rsqrtf(sq * (1.0f / DIM) + 1e-6f);
    float4 gv = ((const float4*)g)[threadIdx.x];
    float4 bv = ((const float4*)b)[threadIdx.x];
    __half2* ph = (__half2*)(outh + (size_t)row * DIM);
    ph[2 * threadIdx.x + 0] = __floats2half2_rn(dx * scale * gv.x + bv.x, dy * scale * gv.y + bv.y);
    ph[2 * threadIdx.x + 1] = __floats2half2_rn(dz * scale * gv.z + bv.z, dw * scale * gv.w + bv.w);
}

// ---------------- LN2: fp16 in + fp16 residual -> fp16 out ----------------
__global__ void ln2_kernel(const __half* __restrict__ in, const __half* __restrict__ res,
                           const float* __restrict__ g, const float* __restrict__ b,
                           __half* __restrict__ outh) {
    __shared__ float sh[8];
    int row = blockIdx.x;
    uint2 raw = ((const uint2*)(in + (size_t)row * DIM))[threadIdx.x];
    uint2 rraw = ((const uint2*)(res + (size_t)row * DIM))[threadIdx.x];
    float2 a0 = __half22float2(*(__half2*)&raw.x);
    float2 a1 = __half22float2(*(__half2*)&raw.y);
    float2 r0 = __half22float2(*(__half2*)&rraw.x);
    float2 r1 = __half22float2(*(__half2*)&rraw.y);
    float4 v = make_float4(a0.x + r0.x, a0.y + r0.y, a1.x + r1.x, a1.y + r1.y);
    float s = block_sum_256(v.x + v.y + v.z + v.w, sh);
    float mean = s * (1.0f / DIM);
    float dx = v.x - mean, dy = v.y - mean, dz = v.z - mean, dw = v.w - mean;
    float sq = block_sum_256(dx*dx + dy*dy + dz*dz + dw*dw, sh);
    float scale = rsqrtf(sq * (1.0f / DIM) + 1e-6f);
    float4 gv = ((const float4*)g)[threadIdx.x];
    float4 bv = ((const float4*)b)[threadIdx.x];
    __half2* ph = (__half2*)(outh + (size_t)row * DIM);
    ph[2 * threadIdx.x + 0] = __floats2half2_rn(dx * scale * gv.x + bv.x, dy * scale * gv.y + bv.y);
    ph[2 * threadIdx.x + 1] = __floats2half2_rn(dz * scale * gv.z + bv.z, dw * scale * gv.w + bv.w);
}

// ---------------- prologue: LN1 + weight transpose + bias concat (1 launch) ----------------
__global__ void prologue(const float* __restrict__ inp,
                         const float* __restrict__ Wq, const float* __restrict__ Wk,
                         const float* __restrict__ Wv, const float* __restrict__ Wfb,
                         const float* __restrict__ Wo,
                         __half* __restrict__ wqkvT, __half* __restrict__ wfbT,
                         __half* __restrict__ woT,
                         const float* __restrict__ bq, const float* __restrict__ bk,
                         const float* __restrict__ bv, float* __restrict__ bqkv,
                         const float* __restrict__ g1, const float* __restrict__ b1,
                         __half* __restrict__ xhp) {
    __shared__ float sh[8];
    __shared__ float t[32][33];
    int bid = blockIdx.x;
    if (bid < BT) {                        // LN1 row
        ln_row(inp, g1, b1, xhp, bid, sh);
        return;
    }
    int idx = bid - BT;
    int xblk = idx & 31;
    int seg  = idx >> 5;                   // 0..192
    int tid = threadIdx.x;
    if (seg == 192) {                      // bias concat
        int i = xblk * 256 + tid;
        if (i < DIM) bqkv[i] = bq[i];
        else if (i < 2 * DIM) bqkv[i] = bk[i - DIM];
        else if (i < 3 * DIM) bqkv[i] = bv[i - 2 * DIM];
        return;
    }
    const float* W;
    __half* WT;
    int R, rb;
    if (seg < 32)       { W = Wq;  WT = wqkvT;                 R = DIM;     rb = seg; }
    else if (seg < 64)  { W = Wk;  WT = wqkvT + DIM * DIM;     R = DIM;     rb = seg - 32; }
    else if (seg < 96)  { W = Wv;  WT = wqkvT + 2 * DIM * DIM; R = DIM;     rb = seg - 64; }
    else if (seg < 160) { W = Wfb; WT = wfbT;                  R = 2 * DIM; rb = seg - 96; }
    else                { W = Wo;  WT = woT;                   R = DIM;     rb = seg - 160; }
    int c0 = xblk * 32, r0 = rb * 32;
    int x = tid & 31, y = tid >> 5;
    #pragma unroll
    for (int i = 0; i < 32; i += 8)
        t[y + i][x] = W[(size_t)(r0 + y + i) * DIM + c0 + x];
    __syncthreads();
    #pragma unroll
    for (int i = 0; i < 32; i += 8)
        WT[(size_t)(c0 + y + i) * R + r0 + x] = __float2half_rn(t[x][y + i]);
}

// ---------------- fp16 tensor-core GEMM (round-14 form; at legacy-HMMA ceiling) ----------------
#define ASH     72
#define ASTAGE  (128 * ASH)
#define BSTAGE  (128 * ASH)
#define GSMEM_BYTES (3 * (ASTAGE + BSTAGE) * 2)   // 110592 → 2 CTAs/SM

template<typename OUT, bool GELU>
__global__ void __launch_bounds__(128, 2)
gemm_h(const __half* __restrict__ A, const __half* __restrict__ Bt,
       const float* __restrict__ bias, OUT* __restrict__ C, int N, int K) {
    extern __shared__ __align__(16) __half hsm[];
    __half* As = hsm;
    __half* Bs = hsm + 3 * ASTAGE;

    int tid = threadIdx.x;
    int wid = tid >> 5, lane = tid & 31;
    int wm = (wid >> 1) * 64;
    int wn = (wid & 1) * 64;
    int g = lane >> 2, t4 = lane & 3;
    int m0 = blockIdx.y << 7, n0 = blockIdx.x << 7;

    int arow  = (lane & 7) | (((lane >> 3) & 1) << 3);
    int akoff = (lane >> 4) << 3;
    int brow  = (lane & 7) | ((lane >> 4) << 3);
    int bkoff = ((lane >> 3) & 1) << 3;
    uint32_t a_lane = smem_u32(As) + (uint32_t)(((wm + arow) * ASH + akoff) << 1);
    uint32_t b_lane = smem_u32(Bs) + (uint32_t)(((wn + brow) * ASH + bkoff) << 1);

    float acc[4][8][4];
    #pragma unroll
    for (int i = 0; i < 4; i++)
        #pragma unroll
        for (int j = 0; j < 8; j++)
            #pragma unroll
            for (int q = 0; q < 4; q++) acc[i][j][q] = 0.0f;

    auto cp_stage = [&](int s, int c) {
        const __half* Ab = A + (size_t)m0 * K + c * 64;
        const __half* Bb = Bt + (size_t)n0 * K + c * 64;
        #pragma unroll
        for (int j = 0; j < 8; j++) {
            int idx = tid + (j << 7);
            int r = idx >> 3, cc = (idx & 7) << 3;
            CP16(smem_u32(As + s * ASTAGE + r * ASH + cc), Ab + (size_t)r * K + cc);
            CP16(smem_u32(Bs + s * BSTAGE + r * ASH + cc), Bb + (size_t)r * K + cc);
        }
        CP_COMMIT();
    };

    int NC = K >> 6;
    cp_stage(0, 0);
    cp_stage(1, 1);

    for (int c = 0; c < NC; c++) {
        CP_WAIT1();
        __syncthreads();
        if (c + 2 < NC) cp_stage((c + 2) % 3, c + 2);
        else CP_COMMIT();

        int s = c % 3;
        uint32_t as_s = a_lane + (uint32_t)(s * ASTAGE * 2);
        uint32_t bs_s = b_lane + (uint32_t)(s * BSTAGE * 2);
        #pragma unroll
        for (int kk = 0; kk < 4; kk++) {
            uint32_t af[4][4], bf[8][2];
            #pragma unroll
            for (int mt = 0; mt < 4; mt++)
                LDSM4(af[mt][0], af[mt][1], af[mt][2], af[mt][3],
                      as_s + (uint32_t)(((mt * 16 * ASH) + kk * 16) << 1));
            #pragma unroll
            for (int np = 0; np < 4; np++)
                LDSM4(bf[2 * np][0], bf[2 * np][1], bf[2 * np + 1][0], bf[2 * np + 1][1],
                      bs_s + (uint32_t)(((np * 16 * ASH) + kk * 16) << 1));
            #pragma unroll
            for (int mt = 0; mt < 4; mt++)
                #pragma unroll
                for (int nt = 0; nt < 8; nt++)
                    mma_fp16(acc[mt][nt], af[mt], bf[nt]);
        }
    }

    #pragma unroll
    for (int mt = 0; mt < 4; mt++) {
        int row = m0 + wm + mt * 16 + g;
        #pragma unroll
        for (int nt = 0; nt < 8; nt++) {
            int col = n0 + wn + nt * 8 + 2 * t4;
            float b0 = bias[col], b1 = bias[col + 1];
            float v00 = acc[mt][nt][0] + b0, v01 = acc[mt][nt][1] + b1;
            float v10 = acc[mt][nt][2] + b0, v11 = acc[mt][nt][3] + b1;
            if (GELU) {
                v00 = gelu_exact(v00); v01 = gelu_exact(v01);
                v10 = gelu_exact(v10); v11 = gelu_exact(v11);
            }
            if (sizeof(OUT) == 2) {
                *(__half2*)((__half*)C + (size_t)row * N + col) = __floats2half2_rn(v00, v01);
                *(__half2*)((__half*)C + (size_t)(row + 8) * N + col) = __floats2half2_rn(v10, v11);
            } else {
                *(float2*)((float*)C + (size_t)row * N + col) = make_float2(v00, v01);
                *(float2*)((float*)C + (size_t)(row + 8) * N + col) = make_float2(v10, v11);
            }
        }
    }
}

// ---------------- local windowed attention (round-14 version) ----------------
__global__ void attn_kernel(const __half* __restrict__ qkv, __half* __restrict__ cat) {
    int w = (blockIdx.x * blockDim.x + threadIdx.x) >> 5;
    int lane = threadIdx.x & 31;
    int dir = w & 1;
    int hp  = (w >> 1) & 7;
    int tg  = w >> 4;
    int b   = tg >> 12;
    int t   = tg & (TT - 1);
    int step = dir ? 1 : -1;
    int base = b << 12;
    int off = hp * 128 + (lane >> 4) * 64 + (lane & 15) * 4;

    int tq = t + step;
    float4 qv = make_float4(0.f, 0.f, 0.f, 0.f);
    if (tq >= 0 && tq < TT) {
        uint2 raw = *(const uint2*)(qkv + (size_t)(base + tq) * 3072 + off);
        float2 a = __half22float2(*(__half2*)&raw.x);
        float2 c = __half22float2(*(__half2*)&raw.y);
        qv = make_float4(a.x, a.y, c.x, c.y);
    }

    float s[3];
    uint2 vr[3];
    #pragma unroll
    for (int j = 0; j < 3; j++) {
        int tk = t + step * j;
        float4 kv = make_float4(0.f, 0.f, 0.f, 0.f);
        uint2 vraw = make_uint2(0u, 0u);
        if (tk >= 0 && tk < TT) {
            const __half* rp = qkv + (size_t)(base + tk) * 3072 + off;
            uint2 kraw = *(const uint2*)(rp + DIM);
            vraw = *(const uint2*)(rp + 2 * DIM);
            float2 k0 = __half22float2(*(__half2*)&kraw.x);
            float2 k1 = __half22float2(*(__half2*)&kraw.y);
            kv = make_float4(k0.x, k0.y, k1.x, k1.y);
        }
        float p = qv.x * kv.x + qv.y * kv.y + qv.z * kv.z + qv.w * kv.w;
        #pragma unroll
        for (int o = 8; o; o >>= 1) p += __shfl_xor_sync(0xffffffffu, p, o);
        s[j] = p * 0.125f;
        vr[j] = vraw;
    }
    float m  = fmaxf(s[0], fmaxf(s[1], s[2]));
    float e0 = __expf(s[0] - m), e1 = __expf(s[1] - m), e2 = __expf(s[2] - m);
    float inv = __fdividef(1.0f, e0 + e1 + e2);
    __half2 w0 = __float2half2_rn(e0 * inv);
    __half2 w1 = __float2half2_rn(e1 * inv);
    __half2 w2 = __float2half2_rn(e2 * inv);
    __half2 lo = __hmul2(w0, *(__half2*)&vr[0].x);
    lo = __hfma2(w1, *(__half2*)&vr[1].x, lo);
    lo = __hfma2(w2, *(__half2*)&vr[2].x, lo);
    __half2 hi = __hmul2(w0, *(__half2*)&vr[0].y);
    hi = __hfma2(w1, *(__half2*)&vr[1].y, hi);
    hi = __hfma2(w2, *(__half2*)&vr[2].y, hi);
    uint2 outp;
    *(__half2*)&outp.x = lo;
    *(__half2*)&outp.y = hi;
    *(uint2*)(cat + (size_t)(base + t) * (2 * DIM) + dir * DIM + off) = outp;
}

// ---------------- launch ----------------
extern "C" void kernel_launch(void* const* d_in, const int* in_sizes, int n_in,
                              void* d_out, int out_size) {
    const float* inp = (const float*)d_in[0];
    const float* Wq  = (const float*)d_in[1];
    const float* bq  = (const float*)d_in[2];
    const float* Wk  = (const float*)d_in[3];
    const float* bk  = (const float*)d_in[4];
    const float* Wv  = (const float*)d_in[5];
    const float* bv  = (const float*)d_in[6];
    const float* Wfb = (const float*)d_in[7];
    const float* bfb = (const float*)d_in[8];
    const float* Wo  = (const float*)d_in[9];
    const float* bo  = (const float*)d_in[10];
    const float* g1  = (const float*)d_in[11];
    const float* b1  = (const float*)d_in[12];
    const float* g2  = (const float*)d_in[13];
    const float* b2  = (const float*)d_in[14];
    float* out = (float*)d_out;

    float *bqkvp;
    __half *xhp, *qkvp, *catp, *fbhp, *yhp, *wqkvT, *wfbT, *woT;
    cudaGetSymbolAddress((void**)&xhp,   g_xh);
    cudaGetSymbolAddress((void**)&qkvp,  g_qkv);
    cudaGetSymbolAddress((void**)&catp,  g_cat);
    cudaGetSymbolAddress((void**)&fbhp,  g_fbh);
    cudaGetSymbolAddress((void**)&yhp,   g_yh);
    cudaGetSymbolAddress((void**)&wqkvT, g_wqkvT);
    cudaGetSymbolAddress((void**)&wfbT,  g_wfbT);
    cudaGetSymbolAddress((void**)&woT,   g_woT);
    cudaGetSymbolAddress((void**)&bqkvp, g_bqkv);

    cudaFuncSetAttribute(gemm_h<__half, false>, cudaFuncAttributeMaxDynamicSharedMemorySize, GSMEM_BYTES);
    cudaFuncSetAttribute(gemm_h<float, true>,   cudaFuncAttributeMaxDynamicSharedMemorySize, GSMEM_BYTES);

    // LN1 + weight transpose + bias concat, one launch
    prologue<<<BT + 193 * 32, 256>>>(inp, Wq, Wk, Wv, Wfb, Wo,
                                     wqkvT, wfbT, woT, bq, bk, bv, bqkvp,
                                     g1, b1, xhp);

    // fused QKV projection: [8192,1024] @ [1024,3072]
    gemm_h<__half, false><<<dim3(3 * DIM / 128, BT / 128), 128, GSMEM_BYTES>>>(
        xhp, wqkvT, bqkvp, qkvp, 3 * DIM, DIM);

    // attention
    attn_kernel<<<BT * 16 / 8, 256>>>(qkvp, catp);

    // feedback projection: K=2048, fp16 out
    gemm_h<__half, false><<<dim3(DIM / 128, BT / 128), 128, GSMEM_BYTES>>>(
        catp, wfbT, bfb, fbhp, DIM, 2 * DIM);

    // residual + LN2 (all-fp16 traffic)
    ln2_kernel<<<BT, 256>>>(fbhp, xhp, g2, b2, yhp);

    // output projection + GELU (fp32 out)
    gemm_h<float, true><<<dim3(DIM / 128, BT / 128), 128, GSMEM_BYTES>>>(
        yhp, woT, bo, out, DIM, DIM);
}